// round 9
// baseline (speedup 1.0000x reference)
#include <cuda_runtime.h>
#include <math.h>

#define N_NODES  50000
#define N_EDGES  400000
#define NCH      16
#define RCUT     10.0f
#define MAX_DEG  64
#define TOTAL_EK (N_EDGES * NCH)            // 6400000
#define OUT1_OFF (N_NODES * NCH)            // 800000
#define OUT2_OFF (N_NODES * NCH * 4)        // 3200000
#define WPB      8                          // warps (=nodes) per block

// ---- scratch (__device__ globals: no allocation allowed) ----
__device__ float  g_dist[N_EDGES];
__device__ int    g_cnt[N_NODES];                 // degree by src (zero at entry, reset by gather)
__device__ float4 g_rec4[N_NODES * MAX_DEG];      // (ux,uy,uz, dst-as-bits) bucketed by src
__device__ int    g_rece[N_NODES * MAX_DEG];      // original edge id per slot
__device__ float  g_rho[TOTAL_EK];                // rho[e*16+k], linear

// geometry + direct bucket scatter of edge records
__global__ void geom_kernel(const float* __restrict__ pos,
                            const int* __restrict__ ei) {
    int e = blockIdx.x * blockDim.x + threadIdx.x;
    if (e >= N_EDGES) return;
    int s = ei[e];
    int d = ei[N_EDGES + e];
    float rx = pos[3 * s + 0] - pos[3 * d + 0];
    float ry = pos[3 * s + 1] - pos[3 * d + 1];
    float rz = pos[3 * s + 2] - pos[3 * d + 2];
    float d2 = rx * rx + ry * ry + rz * rz;
    float inv = rsqrtf(d2);
    g_dist[e] = d2 * inv;
    int rank = atomicAdd(&g_cnt[s], 1);
    int slot = s * MAX_DEG + rank;
    g_rec4[slot] = make_float4(rx * inv, ry * inv, rz * inv, __int_as_float(d));
    g_rece[slot] = e;
}

// radial basis, faithful [K,E]->[E,K] reshape quirk; coalesced read AND write
__global__ void rho_kernel() {
    int idx = blockIdx.x * blockDim.x + threadIdx.x;
    if (idx >= TOTAL_EK) return;
    int n_idx = idx / N_EDGES;
    int e_idx = idx - n_idx * N_EDGES;
    float rr  = g_dist[e_idx];
    g_rho[idx] = 0.44721359549995794f *
                 __sinf((float)(n_idx + 1) * ((float)M_PI / RCUT) * rr) / rr;
}

// gather: ONE WARP PER NODE; half-warp h handles edges 2j+h, lanes k=0..15 are
// channels. Direct scalar LDGs (no staging). shfl-merge + staged f4 epilogue.
__global__ void __launch_bounds__(256)
gather_kernel(const float* __restrict__ h0,
              const float* __restrict__ h1,
              const float* __restrict__ h2,
              float* __restrict__ out) {
    __shared__ float4 sh[WPB * 52];        // epilogue staging only

    int warpid = threadIdx.x >> 5;
    int lane   = threadIdx.x & 31;
    int half   = lane >> 4;
    int k      = lane & 15;
    int n      = blockIdx.x * WPB + warpid;   // grid covers exactly N_NODES

    int cnt = g_cnt[n];
    int off = n * MAX_DEG;

    float a0 = 0.0f;
    float a1x = 0.0f, a1y = 0.0f, a1z = 0.0f;
    float a2[9] = {0,0,0,0,0,0,0,0,0};

    int jmax = (cnt + 1) >> 1;
    for (int j = 0; j < jmax; ++j) {
        int idx2 = 2 * j + half;
        bool valid = idx2 < cnt;
        int slot = off + (valid ? idx2 : 0);

        float4 rec = g_rec4[slot];             // broadcast within half-warp
        int    e   = g_rece[slot];
        int dst = __float_as_int(rec.w);
        float ux = rec.x, uy = rec.y, uz = rec.z;

        float rho = 0.0f;
        if (valid) rho = __ldg(g_rho + e * NCH + k);   // 64B contiguous per half

        int base = dst * NCH + k;
        float s = __ldg(h0 + base);
        const float* vp = h1 + base * 3;
        float vx = __ldg(vp + 0), vy = __ldg(vp + 1), vz = __ldg(vp + 2);
        const float* Mp = h2 + base * 9;
        float M00 = __ldg(Mp + 0), M01 = __ldg(Mp + 1), M02 = __ldg(Mp + 2);
        float M10 = __ldg(Mp + 3), M11 = __ldg(Mp + 4), M12 = __ldg(Mp + 5);
        float M20 = __ldg(Mp + 6), M21 = __ldg(Mp + 7), M22 = __ldg(Mp + 8);

        float vd = vx * ux + vy * uy + vz * uz;
        float tr = M00 + M11 + M22;
        float Mux  = M00 * ux + M01 * uy + M02 * uz;
        float Muy  = M10 * ux + M11 * uy + M12 * uz;
        float Muz  = M20 * ux + M21 * uy + M22 * uz;
        float Mtux = M00 * ux + M10 * uy + M20 * uz;
        float Mtuy = M01 * ux + M11 * uy + M21 * uz;
        float Mtuz = M02 * ux + M12 * uy + M22 * uz;
        float uMu  = ux * Mux + uy * Muy + uz * Muz;

        a0 += rho * (2.0f * s + vd + 2.0f * tr + 2.0f * uMu);

        float c1 = rho * (s + 2.0f * vd + tr);
        a1x += c1 * ux + rho * (2.0f * vx + Mux + Mtux);
        a1y += c1 * uy + rho * (2.0f * vy + Muy + Mtuy);
        a1z += c1 * uz + rho * (2.0f * vz + Muz + Mtuz);

        float ct = rho * (s + tr);
        float ax = ct * ux + rho * (vx + 2.0f * (Mux + Mtux));
        float ay = ct * uy + rho * (vy + 2.0f * (Muy + Mtuy));
        float az = ct * uz + rho * (vz + 2.0f * (Muz + Mtuz));
        float r2m = 2.0f * rho;
        a2[0] += r2m * M00 + ax * ux;
        a2[1] += r2m * M01 + ax * uy;
        a2[2] += r2m * M02 + ax * uz;
        a2[3] += r2m * M10 + ay * ux;
        a2[4] += r2m * M11 + ay * uy;
        a2[5] += r2m * M12 + ay * uz;
        a2[6] += r2m * M20 + az * ux;
        a2[7] += r2m * M21 + az * uy;
        a2[8] += r2m * M22 + az * uz;
    }

    // merge the two half-warps (same channels, disjoint edges)
    const unsigned FULL = 0xffffffffu;
    a0  += __shfl_xor_sync(FULL, a0, 16);
    a1x += __shfl_xor_sync(FULL, a1x, 16);
    a1y += __shfl_xor_sync(FULL, a1y, 16);
    a1z += __shfl_xor_sync(FULL, a1z, 16);
    #pragma unroll
    for (int j = 0; j < 9; ++j) a2[j] += __shfl_xor_sync(FULL, a2[j], 16);

    // staged output: per-channel layout in smem, then coalesced f4 stores
    float* w = (float*)(sh + warpid * 52);
    if (half == 0) {
        w[k] = a0;
        w[16 + 3 * k] = a1x; w[17 + 3 * k] = a1y; w[18 + 3 * k] = a1z;
        float* mw = w + 64 + 9 * k;
        #pragma unroll
        for (int j = 0; j < 9; ++j) mw[j] = a2[j];
    }
    __syncwarp();

    const float4* rd = sh + warpid * 52;      // 52 f4 = {out0row, out1row, out2row}
    float4* O0 = (float4*)(out + (size_t)n * 16);
    float4* O1 = (float4*)(out + OUT1_OFF + (size_t)n * 48);
    float4* O2 = (float4*)(out + OUT2_OFF + (size_t)n * 144);
    {
        float4 val = rd[lane];
        float4* p = (lane < 4) ? (O0 + lane)
                  : ((lane < 16) ? (O1 + lane - 4) : (O2 + lane - 16));
        *p = val;
    }
    {
        int t = lane + 32;                     // 32..51
        if (t < 52) O2[t - 16] = rd[t];
    }

    if (lane == 0) g_cnt[n] = 0;               // reset for next launch
}

extern "C" void kernel_launch(void* const* d_in, const int* in_sizes, int n_in,
                              void* d_out, int out_size) {
    const float* h0  = (const float*)d_in[0];
    const float* h1  = (const float*)d_in[1];
    const float* h2  = (const float*)d_in[2];
    const float* pos = (const float*)d_in[3];
    // d_in[4] = channel_weights (provably unused by reference output)
    const int*   ei  = (const int*)d_in[5];
    float* out = (float*)d_out;

    geom_kernel<<<(N_EDGES + 255) / 256, 256>>>(pos, ei);
    rho_kernel<<<(TOTAL_EK + 255) / 256, 256>>>();
    gather_kernel<<<N_NODES / WPB, 32 * WPB>>>(h0, h1, h2, out);
}